// round 1
// baseline (speedup 1.0000x reference)
#include <cuda_runtime.h>
#include <math.h>

#define T_LEN 32768
#define I_DIM 128
#define H_DIM 512
#define G_DIM 2048
#define NHEAD 25
#define NCTA 64
#define RING 8

// Device-global scratch (no allocation allowed in kernel_launch).
__device__ float        g_xg[T_LEN * G_DIM];     // permuted pre-activations (268 MB)
__device__ float        g_part[T_LEN * NCTA];    // per-step per-CTA head partials (8 MB)
__device__ float        g_v[H_DIM];              // fused head vector v = W1^T Wout^T
__device__ float        g_c0;                    // fused head constant b1 . Wout
__device__ float        g_hring[RING][H_DIM];    // h double(8)-buffer ring
__device__ unsigned int g_counter;               // step-completion counter

// ---------------------------------------------------------------------------
// Kernel 0: fuse head weights, zero ring + counter (re-run every launch so
// graph replays are deterministic).
// ---------------------------------------------------------------------------
__global__ void prep_kernel(const float* __restrict__ W1,
                            const float* __restrict__ b1,
                            const float* __restrict__ Wout) {
    int tid = threadIdx.x;
    if (tid < H_DIM) {
        float s = 0.f;
        for (int k = 0; k < NHEAD; k++) s += Wout[k] * W1[k * H_DIM + tid];
        g_v[tid] = s;
        for (int m = 0; m < RING; m++) g_hring[m][tid] = 0.f;
    }
    if (tid == 0) {
        float s = 0.f;
        for (int k = 0; k < NHEAD; k++) s += b1[k] * Wout[k];
        g_c0 = s;
        g_counter = 0u;
    }
}

// ---------------------------------------------------------------------------
// Kernel 1: xg[t, colp] = x[t] . W_ih[grow] + (b_ih+b_hh)[grow], written in a
// permuted layout so each LSTM CTA reads 32 contiguous floats per step:
//   colp = c*32 + j, with gate row grow = (j/8)*512 + c*8 + (j%8).
// ---------------------------------------------------------------------------
__global__ __launch_bounds__(256) void xg_kernel(const float* __restrict__ x,
                                                 const float* __restrict__ W_ih,
                                                 const float* __restrict__ b_ih,
                                                 const float* __restrict__ b_hh) {
    __shared__ float Xs[32][I_DIM];
    int tb   = blockIdx.x;        // 0..1023 (32 timesteps each)
    int cb   = blockIdx.y;        // 0..7    (256 columns each)
    int tid  = threadIdx.x;
    int tbase = tb * 32;

    for (int idx = tid; idx < 32 * I_DIM; idx += 256)
        Xs[idx >> 7][idx & 127] = x[(tbase + (idx >> 7)) * I_DIM + (idx & 127)];
    __syncthreads();

    int col  = cb * 256 + tid;
    int c    = col >> 5;
    int j    = col & 31;
    int grow = (j >> 3) * 512 + c * 8 + (j & 7);
    float bias = b_ih[grow] + b_hh[grow];

    float acc[32];
#pragma unroll
    for (int tt = 0; tt < 32; tt++) acc[tt] = bias;

    const float4* Wr = (const float4*)(W_ih + grow * I_DIM);
    for (int kq = 0; kq < 32; kq++) {
        float4 w4 = Wr[kq];
#pragma unroll
        for (int tt = 0; tt < 32; tt++) {
            float4 x4 = *(const float4*)&Xs[tt][kq * 4];
            acc[tt] += w4.x * x4.x + w4.y * x4.y + w4.z * x4.z + w4.w * x4.w;
        }
    }
#pragma unroll
    for (int tt = 0; tt < 32; tt++)
        g_xg[(tbase + tt) * G_DIM + col] = acc[tt];
}

// ---------------------------------------------------------------------------
// Kernel 2: persistent sequential LSTM. 64 CTAs x 256 threads; CTA cb owns
// hidden units [8cb, 8cb+8) = 32 gate rows. W_hh slice is register-resident:
// warp w handles rows 4w..4w+3; lane l handles k in {4l+128m+kk}.
// Cross-CTA sync: fence + RED.ADD on g_counter, single-thread volatile poll.
// ---------------------------------------------------------------------------
__global__ __launch_bounds__(256, 1) void lstm_kernel(const float* __restrict__ W_hh) {
    __shared__ float gbuf[32];
    int tid = threadIdx.x;
    int w   = tid >> 5;
    int l   = tid & 31;
    int cb  = blockIdx.x;

    // Load register-resident weights once.
    float4 wr[4][4];
#pragma unroll
    for (int r = 0; r < 4; r++) {
        int j    = 4 * w + r;
        int grow = (j >> 3) * 512 + cb * 8 + (j & 7);
#pragma unroll
        for (int m = 0; m < 4; m++)
            wr[r][m] = *(const float4*)(W_hh + grow * H_DIM + 4 * l + 128 * m);
    }

    float cstate = 0.f;
    float vval   = 0.f;
    if (tid < 8) vval = g_v[cb * 8 + tid];

    for (int t = 0; t < T_LEN; t++) {
        // Prefetch this CTA's 4 xg values per warp (independent of h).
        float4 xg4 = make_float4(0.f, 0.f, 0.f, 0.f);
        if (l == 0) xg4 = *(const float4*)&g_xg[t * G_DIM + cb * 32 + 4 * w];

        // Wait until all CTAs have published h for step t.
        if (tid == 0) {
            unsigned target = (unsigned)t * NCTA;
            while (*((volatile unsigned int*)&g_counter) < target) { }
            __threadfence();
        }
        __syncthreads();

        int slot = t & (RING - 1);
        float4 h4[4];
#pragma unroll
        for (int m = 0; m < 4; m++)
            h4[m] = __ldcg((const float4*)&g_hring[slot][4 * l + 128 * m]);

        float acc[4];
#pragma unroll
        for (int r = 0; r < 4; r++) {
            float s = 0.f;
#pragma unroll
            for (int m = 0; m < 4; m++)
                s += wr[r][m].x * h4[m].x + wr[r][m].y * h4[m].y
                   + wr[r][m].z * h4[m].z + wr[r][m].w * h4[m].w;
            acc[r] = s;
        }
        // Reduce each row's partial across the 32 lanes (k-slices).
#pragma unroll
        for (int off = 16; off > 0; off >>= 1) {
#pragma unroll
            for (int r = 0; r < 4; r++)
                acc[r] += __shfl_xor_sync(0xffffffffu, acc[r], off);
        }
        if (l == 0) {
            gbuf[4 * w + 0] = acc[0] + xg4.x;
            gbuf[4 * w + 1] = acc[1] + xg4.y;
            gbuf[4 * w + 2] = acc[2] + xg4.z;
            gbuf[4 * w + 3] = acc[3] + xg4.w;
        }
        __syncthreads();

        // 8 unit-threads: LSTM cell + h publish + head partial.
        if (tid < 8) {
            float gi = gbuf[tid];
            float gf = gbuf[8 + tid];
            float gg = gbuf[16 + tid];
            float go = gbuf[24 + tid];
            float iv = 1.f / (1.f + expf(-gi));
            float fv = 1.f / (1.f + expf(-gf));
            float gv = tanhf(gg);
            float ov = 1.f / (1.f + expf(-go));
            cstate = fv * cstate + iv * gv;
            float hv = ov * tanhf(cstate);
            __stcg(&g_hring[(t + 1) & (RING - 1)][cb * 8 + tid], hv);
            float part = hv * vval;
#pragma unroll
            for (int off = 4; off > 0; off >>= 1)
                part += __shfl_xor_sync(0x000000ffu, part, off);
            if (tid == 0) g_part[t * NCTA + cb] = part;
        }
        __syncthreads();

        if (tid == 0) {
            __threadfence();           // make h visible before the arrival
            atomicAdd(&g_counter, 1u); // no-return use -> RED
        }
    }
}

// ---------------------------------------------------------------------------
// Kernel 3: out[t] = c0 + sum_c g_part[t][c]
// ---------------------------------------------------------------------------
__global__ void head_kernel(float* __restrict__ out) {
    int t = blockIdx.x * blockDim.x + threadIdx.x;
    if (t >= T_LEN) return;
    float s = g_c0;
    const float4* p = (const float4*)&g_part[t * NCTA];
#pragma unroll
    for (int q = 0; q < NCTA / 4; q++) {
        float4 v = p[q];
        s += v.x + v.y + v.z + v.w;
    }
    out[t] = s;
}

// ---------------------------------------------------------------------------
extern "C" void kernel_launch(void* const* d_in, const int* in_sizes, int n_in,
                              void* d_out, int out_size) {
    const float* x    = (const float*)d_in[0];
    const float* W_ih = (const float*)d_in[1];
    const float* W_hh = (const float*)d_in[2];
    const float* b_ih = (const float*)d_in[3];
    const float* b_hh = (const float*)d_in[4];
    const float* W1   = (const float*)d_in[5];
    const float* b1   = (const float*)d_in[6];
    const float* Wout = (const float*)d_in[7];
    float* out = (float*)d_out;

    (void)in_sizes; (void)n_in; (void)out_size;

    prep_kernel<<<1, 512>>>(W1, b1, Wout);
    dim3 gx(T_LEN / 32, G_DIM / 256);
    xg_kernel<<<gx, 256>>>(x, W_ih, b_ih, b_hh);
    lstm_kernel<<<NCTA, 256>>>(W_hh);
    head_kernel<<<T_LEN / 256, 256>>>(out);
}

// round 2
// speedup vs baseline: 1.5114x; 1.5114x over previous
#include <cuda_runtime.h>
#include <math.h>

#define T_LEN 32768
#define I_DIM 128
#define H_DIM 512
#define G_DIM 2048
#define NHEAD 25
#define NCTA 64
#define RING 8

// Device-global scratch (no allocation allowed anywhere).
__device__ float g_xg[T_LEN * G_DIM];                    // permuted pre-activations (268 MB)
__device__ float g_part[T_LEN * H_DIM];                  // per-step per-unit head partials (64 MB)
__device__ float g_v[H_DIM];                             // fused head vector v = W1^T Wout^T
__device__ float g_c0;                                   // fused head constant b1 . Wout
__device__ __align__(128) float g_hring[RING][H_DIM];    // h ring buffer
__device__ __align__(128) unsigned int g_counter;        // step-completion counter

// f32x2 packed FMA (sm_100+): d = a*b + c on two packed floats.
__device__ __forceinline__ unsigned long long fma2(unsigned long long a,
                                                   unsigned long long b,
                                                   unsigned long long c) {
    unsigned long long d;
    asm("fma.rn.f32x2 %0, %1, %2, %3;" : "=l"(d) : "l"(a), "l"(b), "l"(c));
    return d;
}

__device__ __forceinline__ float fsigmoid(float x) {
    return __fdividef(1.f, 1.f + __expf(-x));
}
__device__ __forceinline__ float ftanh_fast(float x) {
    // 1 - 2/(e^{2x}+1); saturates cleanly at +-1 for large |x| (no inf/inf).
    return 1.f - 2.f * __fdividef(1.f, __expf(2.f * x) + 1.f);
}

// ---------------------------------------------------------------------------
// Kernel 0: fuse head weights, zero ring + counter (every launch -> graph-safe).
// ---------------------------------------------------------------------------
__global__ void prep_kernel(const float* __restrict__ W1,
                            const float* __restrict__ b1,
                            const float* __restrict__ Wout) {
    int tid = threadIdx.x;
    if (tid < H_DIM) {
        float s = 0.f;
        for (int k = 0; k < NHEAD; k++) s += Wout[k] * W1[k * H_DIM + tid];
        g_v[tid] = s;
        for (int m = 0; m < RING; m++) g_hring[m][tid] = 0.f;
    }
    if (tid == 0) {
        float s = 0.f;
        for (int k = 0; k < NHEAD; k++) s += b1[k] * Wout[k];
        g_c0 = s;
        g_counter = 0u;
    }
}

// ---------------------------------------------------------------------------
// Kernel 1: xg[t, colp] = x[t] . W_ih[grow] + (b_ih+b_hh)[grow], permuted so
// warp u of the LSTM kernel reads one float4 (i,f,g,o for its unit):
//   colp = u*4 + gate,  grow = gate*512 + u.
// ---------------------------------------------------------------------------
__global__ __launch_bounds__(256) void xg_kernel(const float* __restrict__ x,
                                                 const float* __restrict__ W_ih,
                                                 const float* __restrict__ b_ih,
                                                 const float* __restrict__ b_hh) {
    __shared__ float Xs[32][I_DIM];
    int tb    = blockIdx.x;       // 0..1023 (32 timesteps each)
    int cb    = blockIdx.y;       // 0..7    (256 columns each)
    int tid   = threadIdx.x;
    int tbase = tb * 32;

    for (int idx = tid; idx < 32 * I_DIM; idx += 256)
        Xs[idx >> 7][idx & 127] = x[(tbase + (idx >> 7)) * I_DIM + (idx & 127)];
    __syncthreads();

    int col  = cb * 256 + tid;            // permuted column
    int u    = col >> 2;
    int gate = col & 3;
    int grow = gate * 512 + u;
    float bias = b_ih[grow] + b_hh[grow];

    float acc[32];
#pragma unroll
    for (int tt = 0; tt < 32; tt++) acc[tt] = bias;

    const float4* Wr = (const float4*)(W_ih + grow * I_DIM);
    for (int kq = 0; kq < 32; kq++) {
        float4 w4 = Wr[kq];
#pragma unroll
        for (int tt = 0; tt < 32; tt++) {
            float4 x4 = *(const float4*)&Xs[tt][kq * 4];
            acc[tt] += w4.x * x4.x + w4.y * x4.y + w4.z * x4.z + w4.w * x4.w;
        }
    }
#pragma unroll
    for (int tt = 0; tt < 32; tt++)
        g_xg[(tbase + tt) * G_DIM + col] = acc[tt];
}

// ---------------------------------------------------------------------------
// Kernel 2: persistent sequential LSTM. 64 CTAs x 256 threads.
// Warp w of CTA cb owns hidden unit u = cb*8+w (gate rows u, 512+u, 1024+u,
// 1536+u). W_hh slice register-resident (64 floats/lane). Per step:
//   tid0 acquire-polls counter -> bar -> cooperative h stage to smem (2KB,
//   each L2 line read ONCE per CTA) -> bar -> packed-f32x2 matvec + shfl
//   reduce -> lane0 runs the LSTM cell, publishes h + head partial -> bar ->
//   tid0 red.release arrival. No membar/CCTL.IVALL anywhere.
// ---------------------------------------------------------------------------
__global__ __launch_bounds__(256, 1) void lstm_kernel(const float* __restrict__ W_hh) {
    __shared__ float hbuf[H_DIM];
    int tid = threadIdx.x;
    int w   = tid >> 5;
    int l   = tid & 31;
    int cb  = blockIdx.x;
    int u   = cb * 8 + w;

    // Register-resident W_hh: row r (gate) covers h[4l+128m .. +4).
    float4 wr[4][4];
#pragma unroll
    for (int r = 0; r < 4; r++) {
        const float* row = W_hh + (r * 512 + u) * H_DIM;
#pragma unroll
        for (int m = 0; m < 4; m++)
            wr[r][m] = *(const float4*)(row + 4 * l + 128 * m);
    }

    float cstate = 0.f;
    float vval   = (l == 0) ? g_v[u] : 0.f;

    float4 xg4 = make_float4(0.f, 0.f, 0.f, 0.f);
    if (l == 0) xg4 = *(const float4*)&g_xg[0 * G_DIM + u * 4];   // prefetch t=0

    for (int t = 0; t < T_LEN; t++) {
        // Prefetch next step's gate pre-activations (DRAM latency hidden).
        float4 xg_next = make_float4(0.f, 0.f, 0.f, 0.f);
        if (l == 0 && t + 1 < T_LEN)
            xg_next = *(const float4*)&g_xg[(t + 1) * G_DIM + u * 4];

        // Wait for all CTAs to have finished step t-1 (acquire, no L1 flush).
        if (tid == 0) {
            unsigned target = (unsigned)t * NCTA;
            unsigned cnt;
            do {
                asm volatile("ld.acquire.gpu.global.u32 %0, [%1];"
                             : "=r"(cnt) : "l"(&g_counter));
            } while (cnt < target);
        }
        __syncthreads();

        // Cooperative stage of h into smem: 256 threads x 8B, L1-bypassed.
        int slot = t & (RING - 1);
        float2 st2 = __ldcg((const float2*)&g_hring[slot][2 * tid]);
        *(float2*)&hbuf[2 * tid] = st2;
        __syncthreads();

        // Matvec: 4 gate rows x 16 h-elems per lane, packed f32x2.
        unsigned long long acc2[4] = {0ull, 0ull, 0ull, 0ull};
#pragma unroll
        for (int m = 0; m < 4; m++) {
            float4 h4 = *(const float4*)&hbuf[4 * l + 128 * m];   // conflict-free
            unsigned long long hlo, hhi;
            hlo = *(const unsigned long long*)&h4.x;
            hhi = *(const unsigned long long*)&h4.z;
#pragma unroll
            for (int r = 0; r < 4; r++) {
                unsigned long long wlo = *(const unsigned long long*)&wr[r][m].x;
                unsigned long long whi = *(const unsigned long long*)&wr[r][m].z;
                acc2[r] = fma2(wlo, hlo, acc2[r]);
                acc2[r] = fma2(whi, hhi, acc2[r]);
            }
        }
        float acc[4];
#pragma unroll
        for (int r = 0; r < 4; r++) {
            unsigned int lo = (unsigned int)acc2[r];
            unsigned int hi = (unsigned int)(acc2[r] >> 32);
            acc[r] = __uint_as_float(lo) + __uint_as_float(hi);
        }
#pragma unroll
        for (int off = 16; off > 0; off >>= 1) {
#pragma unroll
            for (int r = 0; r < 4; r++)
                acc[r] += __shfl_xor_sync(0xffffffffu, acc[r], off);
        }

        // Lane 0 of each warp: full LSTM cell for its unit.
        if (l == 0) {
            float iv = fsigmoid(acc[0] + xg4.x);
            float fv = fsigmoid(acc[1] + xg4.y);
            float gv = ftanh_fast(acc[2] + xg4.z);
            float ov = fsigmoid(acc[3] + xg4.w);
            cstate = fv * cstate + iv * gv;
            float hv = ov * ftanh_fast(cstate);
            __stcg(&g_hring[(t + 1) & (RING - 1)][u], hv);
            __stcg(&g_part[t * H_DIM + u], hv * vval);
        }
        xg4 = xg_next;
        __syncthreads();   // all 8 units' h published before the arrival

        if (tid == 0) {
            asm volatile("red.release.gpu.global.add.u32 [%0], %1;"
                         :: "l"(&g_counter), "r"(1u) : "memory");
        }
    }
}

// ---------------------------------------------------------------------------
// Kernel 3: out[t] = c0 + sum_u g_part[t][u]
// ---------------------------------------------------------------------------
__global__ void head_kernel(float* __restrict__ out) {
    int t = blockIdx.x * blockDim.x + threadIdx.x;
    if (t >= T_LEN) return;
    float s = g_c0;
    const float4* p = (const float4*)&g_part[t * H_DIM];
#pragma unroll 8
    for (int q = 0; q < H_DIM / 4; q++) {
        float4 v = p[q];
        s += v.x + v.y + v.z + v.w;
    }
    out[t] = s;
}

// ---------------------------------------------------------------------------
extern "C" void kernel_launch(void* const* d_in, const int* in_sizes, int n_in,
                              void* d_out, int out_size) {
    const float* x    = (const float*)d_in[0];
    const float* W_ih = (const float*)d_in[1];
    const float* W_hh = (const float*)d_in[2];
    const float* b_ih = (const float*)d_in[3];
    const float* b_hh = (const float*)d_in[4];
    const float* W1   = (const float*)d_in[5];
    const float* b1   = (const float*)d_in[6];
    const float* Wout = (const float*)d_in[7];
    float* out = (float*)d_out;

    (void)in_sizes; (void)n_in; (void)out_size;

    prep_kernel<<<1, 512>>>(W1, b1, Wout);
    dim3 gx(T_LEN / 32, G_DIM / 256);
    xg_kernel<<<gx, 256>>>(x, W_ih, b_ih, b_hh);
    lstm_kernel<<<NCTA, 256>>>(W_hh);
    head_kernel<<<T_LEN / 256, 256>>>(out);
}

// round 5
// speedup vs baseline: 1.7073x; 1.1297x over previous
#include <cuda_runtime.h>
#include <math.h>

#define T_LEN 32768
#define I_DIM 128
#define H_DIM 512
#define G_DIM 2048
#define NHEAD 25
#define NCTA 64
#define RING 8

// Device-global scratch (no allocation allowed anywhere).
__device__ float  g_xg[T_LEN * G_DIM];                 // permuted pre-activations (268 MB)
__device__ float  g_part[T_LEN * NCTA];                // per-step per-CTA head partials (8 MB)
__device__ float  g_v[H_DIM];                          // fused head vector v = W1^T Wout^T
__device__ float  g_c0;                                // fused head constant b1 . Wout
// (h value bits in low 32, step tag in high 32) — single 8B word => atomic.
__device__ __align__(128) unsigned long long g_hpair[RING][H_DIM];

// f32x2 packed FMA (sm_100+): d = a*b + c on two packed floats.
__device__ __forceinline__ unsigned long long fma2(unsigned long long a,
                                                   unsigned long long b,
                                                   unsigned long long c) {
    unsigned long long d;
    asm("fma.rn.f32x2 %0, %1, %2, %3;" : "=l"(d) : "l"(a), "l"(b), "l"(c));
    return d;
}

__device__ __forceinline__ float fsigmoid(float x) {
    return __fdividef(1.f, 1.f + __expf(-x));
}
__device__ __forceinline__ float ftanh_fast(float x) {
    // 1 - 2/(e^{2x}+1); saturates cleanly at +-1 for large |x|.
    return 1.f - 2.f * __fdividef(1.f, __expf(2.f * x) + 1.f);
}

// ---------------------------------------------------------------------------
// Kernel 0: fuse head weights; re-init ALL ring words (graph-replay safe).
// ---------------------------------------------------------------------------
__global__ void prep_kernel(const float* __restrict__ W1,
                            const float* __restrict__ b1,
                            const float* __restrict__ Wout) {
    int tid = threadIdx.x;
    if (tid < H_DIM) {
        float s = 0.f;
        for (int k = 0; k < NHEAD; k++) s += Wout[k] * W1[k * H_DIM + tid];
        g_v[tid] = s;
        // slot 0 carries h(0)=0 with tag 0 (consumed at t=0); others poisoned.
        g_hpair[0][tid] = 0ull;                       // h=0.0f bits, tag=0
        for (int m = 1; m < RING; m++)
            g_hpair[m][tid] = 0xFFFFFFFF00000000ull;  // tag=0xFFFFFFFF poison
    }
    if (tid == 0) {
        float s = 0.f;
        for (int k = 0; k < NHEAD; k++) s += b1[k] * Wout[k];
        g_c0 = s;
    }
}

// ---------------------------------------------------------------------------
// Kernel 1: xg[t, colp] = x[t] . W_ih[grow] + (b_ih+b_hh)[grow], permuted so
// warp u of the LSTM kernel reads one float4 (i,f,g,o for its unit):
//   colp = u*4 + gate,  grow = gate*512 + u.
// ---------------------------------------------------------------------------
__global__ __launch_bounds__(256) void xg_kernel(const float* __restrict__ x,
                                                 const float* __restrict__ W_ih,
                                                 const float* __restrict__ b_ih,
                                                 const float* __restrict__ b_hh) {
    __shared__ float Xs[32][I_DIM];
    int tb    = blockIdx.x;       // 0..1023 (32 timesteps each)
    int cb    = blockIdx.y;       // 0..7    (256 columns each)
    int tid   = threadIdx.x;
    int tbase = tb * 32;

    for (int idx = tid; idx < 32 * I_DIM; idx += 256)
        Xs[idx >> 7][idx & 127] = x[(tbase + (idx >> 7)) * I_DIM + (idx & 127)];
    __syncthreads();

    int col  = cb * 256 + tid;            // permuted column
    int u    = col >> 2;
    int gate = col & 3;
    int grow = gate * 512 + u;
    float bias = b_ih[grow] + b_hh[grow];

    float acc[32];
#pragma unroll
    for (int tt = 0; tt < 32; tt++) acc[tt] = bias;

    const float4* Wr = (const float4*)(W_ih + grow * I_DIM);
    for (int kq = 0; kq < 32; kq++) {
        float4 w4 = Wr[kq];
#pragma unroll
        for (int tt = 0; tt < 32; tt++) {
            float4 x4 = *(const float4*)&Xs[tt][kq * 4];
            acc[tt] += w4.x * x4.x + w4.y * x4.y + w4.z * x4.z + w4.w * x4.w;
        }
    }
#pragma unroll
    for (int tt = 0; tt < 32; tt++)
        g_xg[(tbase + tt) * G_DIM + col] = acc[tt];
}

// ---------------------------------------------------------------------------
// Kernel 2: persistent sequential LSTM. 64 CTAs x 256 threads.
// Warp w of CTA cb owns unit u = cb*8+w (gate rows u, 512+u, 1024+u, 1536+u),
// W_hh slice register-resident. Sync per step: producers publish (h, tag=t+1)
// as ONE scalar 8B st.relaxed.gpu (single-copy atomic -> no torn tag/h);
// consumers poll the two pairs they own with scalar 8B ld.relaxed.gpu and
// stage h into smem. No counter, no fences, no separate data load.
// Ring safety: publishing tag t+1 to slot (t+1)%8 requires this CTA passed
// the step-t poll, i.e. every CTA finished step t-1, hence every CTA already
// consumed slot (t+1)%8's previous tag t-7 at its step t-7.
// ---------------------------------------------------------------------------
__global__ __launch_bounds__(256, 1) void lstm_kernel(const float* __restrict__ W_hh) {
    __shared__ float hbuf[H_DIM];
    __shared__ float pbuf[8];
    int tid = threadIdx.x;
    int w   = tid >> 5;
    int l   = tid & 31;
    int cb  = blockIdx.x;
    int u   = cb * 8 + w;

    // Register-resident W_hh: row r (gate) covers h[4l+128m .. +4).
    float4 wr[4][4];
#pragma unroll
    for (int r = 0; r < 4; r++) {
        const float* row = W_hh + (r * 512 + u) * H_DIM;
#pragma unroll
        for (int m = 0; m < 4; m++)
            wr[r][m] = *(const float4*)(row + 4 * l + 128 * m);
    }

    float cstate = 0.f;
    float vval   = (l == 0) ? g_v[u] : 0.f;

    float4 xg4 = make_float4(0.f, 0.f, 0.f, 0.f);
    if (l == 0) xg4 = *(const float4*)&g_xg[0 * G_DIM + u * 4];   // prefetch t=0

    for (int t = 0; t < T_LEN; t++) {
        // Prefetch next step's gate pre-activations (DRAM latency hidden).
        float4 xg_next = make_float4(0.f, 0.f, 0.f, 0.f);
        if (l == 0 && t + 1 < T_LEN)
            xg_next = *(const float4*)&g_xg[(t + 1) * G_DIM + u * 4];

        // Poll the 2 pairs this thread owns (scalar atomic 8B relaxed loads).
        {
            const unsigned long long* p0 = &g_hpair[t & (RING - 1)][2 * tid];
            unsigned long long v0, v1;
            unsigned long long want = ((unsigned long long)(unsigned)t) << 32;
            do {
                asm volatile("ld.relaxed.gpu.global.b64 %0, [%1];"
                             : "=l"(v0) : "l"(p0) : "memory");
                asm volatile("ld.relaxed.gpu.global.b64 %0, [%1];"
                             : "=l"(v1) : "l"(p0 + 1) : "memory");
            } while ((v0 & 0xFFFFFFFF00000000ull) != want ||
                     (v1 & 0xFFFFFFFF00000000ull) != want);
            hbuf[2 * tid]     = __uint_as_float((unsigned)v0);
            hbuf[2 * tid + 1] = __uint_as_float((unsigned)v1);
        }
        __syncthreads();

        // Matvec: 4 gate rows x 16 h-elems per lane, packed f32x2.
        unsigned long long acc2[4] = {0ull, 0ull, 0ull, 0ull};
#pragma unroll
        for (int m = 0; m < 4; m++) {
            float4 h4 = *(const float4*)&hbuf[4 * l + 128 * m];   // conflict-free
            unsigned long long hlo = *(const unsigned long long*)&h4.x;
            unsigned long long hhi = *(const unsigned long long*)&h4.z;
#pragma unroll
            for (int r = 0; r < 4; r++) {
                unsigned long long wlo = *(const unsigned long long*)&wr[r][m].x;
                unsigned long long whi = *(const unsigned long long*)&wr[r][m].z;
                acc2[r] = fma2(wlo, hlo, acc2[r]);
                acc2[r] = fma2(whi, hhi, acc2[r]);
            }
        }
        float acc[4];
#pragma unroll
        for (int r = 0; r < 4; r++) {
            unsigned int lo = (unsigned int)acc2[r];
            unsigned int hi = (unsigned int)(acc2[r] >> 32);
            acc[r] = __uint_as_float(lo) + __uint_as_float(hi);
        }
#pragma unroll
        for (int off = 16; off > 0; off >>= 1) {
#pragma unroll
            for (int r = 0; r < 4; r++)
                acc[r] += __shfl_xor_sync(0xffffffffu, acc[r], off);
        }

        // Lane 0 of each warp: LSTM cell + fused atomic (h, tag) publish.
        if (l == 0) {
            float iv = fsigmoid(acc[0] + xg4.x);
            float fv = fsigmoid(acc[1] + xg4.y);
            float gv = ftanh_fast(acc[2] + xg4.z);
            float ov = fsigmoid(acc[3] + xg4.w);
            cstate = fv * cstate + iv * gv;
            float hv = ov * ftanh_fast(cstate);
            unsigned long long pairv =
                ((unsigned long long)(unsigned)(t + 1) << 32) |
                (unsigned long long)__float_as_uint(hv);
            asm volatile("st.relaxed.gpu.global.b64 [%0], %1;"
                         :: "l"(&g_hpair[(t + 1) & (RING - 1)][u]), "l"(pairv)
                         : "memory");
            pbuf[w] = hv * vval;
        }
        xg4 = xg_next;
        __syncthreads();   // hbuf reads done; pbuf complete

        if (tid == 0) {    // off critical path: per-CTA head partial
            float s = pbuf[0] + pbuf[1] + pbuf[2] + pbuf[3]
                    + pbuf[4] + pbuf[5] + pbuf[6] + pbuf[7];
            g_part[t * NCTA + cb] = s;
        }
    }
}

// ---------------------------------------------------------------------------
// Kernel 3: out[t] = c0 + sum_cb g_part[t][cb]
// ---------------------------------------------------------------------------
__global__ void head_kernel(float* __restrict__ out) {
    int t = blockIdx.x * blockDim.x + threadIdx.x;
    if (t >= T_LEN) return;
    float s = g_c0;
    const float4* p = (const float4*)&g_part[t * NCTA];
#pragma unroll
    for (int q = 0; q < NCTA / 4; q++) {
        float4 v = p[q];
        s += v.x + v.y + v.z + v.w;
    }
    out[t] = s;
}

// ---------------------------------------------------------------------------
extern "C" void kernel_launch(void* const* d_in, const int* in_sizes, int n_in,
                              void* d_out, int out_size) {
    const float* x    = (const float*)d_in[0];
    const float* W_ih = (const float*)d_in[1];
    const float* W_hh = (const float*)d_in[2];
    const float* b_ih = (const float*)d_in[3];
    const float* b_hh = (const float*)d_in[4];
    const float* W1   = (const float*)d_in[5];
    const float* b1   = (const float*)d_in[6];
    const float* Wout = (const float*)d_in[7];
    float* out = (float*)d_out;

    (void)in_sizes; (void)n_in; (void)out_size;

    prep_kernel<<<1, 512>>>(W1, b1, Wout);
    dim3 gx(T_LEN / 32, G_DIM / 256);
    xg_kernel<<<gx, 256>>>(x, W_ih, b_ih, b_hh);
    lstm_kernel<<<NCTA, 256>>>(W_hh);
    head_kernel<<<T_LEN / 256, 256>>>(out);
}